// round 2
// baseline (speedup 1.0000x reference)
#include <cuda_runtime.h>
#include <stdint.h>

#define TT 512
#define NB 256
#define HH 256
#define GG 1024

__device__ float    g_xw[(size_t)TT * NB * GG];
__device__ float    g_h[2 * NB * HH];
__device__ unsigned g_bar;

__device__ __forceinline__ float cvt_tf32(float x) {
    float r; asm("cvt.rna.tf32.f32 %0, %1;" : "=f"(r) : "f"(x)); return r;
}
__device__ __forceinline__ void mma8(float d[4], uint32_t a0, uint32_t a1,
                                     uint32_t a2, uint32_t a3, uint32_t b0, uint32_t b1) {
    asm volatile("mma.sync.aligned.m16n8k8.row.col.f32.tf32.tf32.f32 "
                 "{%0,%1,%2,%3}, {%4,%5,%6,%7}, {%8,%9}, {%0,%1,%2,%3};\n"
                 : "+f"(d[0]), "+f"(d[1]), "+f"(d[2]), "+f"(d[3])
                 : "r"(a0), "r"(a1), "r"(a2), "r"(a3), "r"(b0), "r"(b1));
}
__device__ __forceinline__ float sigm(float x) { return __fdividef(1.f, 1.f + __expf(-x)); }
__device__ __forceinline__ float tanh_acc(float x) { return 1.f - __fdividef(2.f, __expf(2.f * x) + 1.f); }

// ================= Phase 1: xW = x @ [Wi|Wf|Wg|Wo] + b ====================
__global__ void __launch_bounds__(256) lstm_xw_kernel(
    const float* __restrict__ x,
    const float* __restrict__ w0, const float* __restrict__ w1,
    const float* __restrict__ w2, const float* __restrict__ w3,
    const float* __restrict__ bx0, const float* __restrict__ bh0,
    const float* __restrict__ bx1, const float* __restrict__ bh1,
    const float* __restrict__ bx2, const float* __restrict__ bh2,
    const float* __restrict__ bx3, const float* __restrict__ bh3)
{
    __shared__ float x_s[128 * 36];
    __shared__ float w_s[32 * 72];

    const int tid = threadIdx.x, lane = tid & 31, warp = tid >> 5;
    const int wm = warp >> 1, wn = warp & 1;
    const int row0 = blockIdx.y * 128;
    const int gc0 = blockIdx.x * 64;
    const int gate = gc0 >> 8, jc0 = gc0 & 255;

    const float* wx = (gate == 0) ? w0 : (gate == 1) ? w1 : (gate == 2) ? w2 : w3;
    const float* bx = (gate == 0) ? bx0 : (gate == 1) ? bx1 : (gate == 2) ? bx2 : bx3;
    const float* bh = (gate == 0) ? bh0 : (gate == 1) ? bh1 : (gate == 2) ? bh2 : bh3;

    float acc[2][4][4];
    #pragma unroll
    for (int i = 0; i < 2; i++)
        #pragma unroll
        for (int j = 0; j < 4; j++)
            #pragma unroll
            for (int k = 0; k < 4; k++) acc[i][j][k] = 0.f;

    for (int k0 = 0; k0 < 256; k0 += 32) {
        #pragma unroll
        for (int i = 0; i < 4; i++) {
            int q = i * 256 + tid, r = q >> 3, c4 = (q & 7) << 2;
            float4 v = *(const float4*)(x + (size_t)(row0 + r) * 256 + k0 + c4);
            float* d = x_s + r * 36 + c4;
            d[0] = cvt_tf32(v.x); d[1] = cvt_tf32(v.y);
            d[2] = cvt_tf32(v.z); d[3] = cvt_tf32(v.w);
        }
        #pragma unroll
        for (int i = 0; i < 2; i++) {
            int q = i * 256 + tid, r = q >> 4, c4 = (q & 15) << 2;
            float4 v = *(const float4*)(wx + (size_t)(k0 + r) * 256 + jc0 + c4);
            v.x = cvt_tf32(v.x); v.y = cvt_tf32(v.y);
            v.z = cvt_tf32(v.z); v.w = cvt_tf32(v.w);
            *(float4*)(w_s + r * 72 + c4) = v;
        }
        __syncthreads();
        #pragma unroll
        for (int kk = 0; kk < 4; kk++) {
            const int kb = kk * 8;
            uint32_t a[2][4];
            #pragma unroll
            for (int mt = 0; mt < 2; mt++) {
                int ar = wm * 32 + mt * 16 + (lane >> 2);
                a[mt][0] = __float_as_uint(x_s[ar * 36 + kb + (lane & 3)]);
                a[mt][1] = __float_as_uint(x_s[(ar + 8) * 36 + kb + (lane & 3)]);
                a[mt][2] = __float_as_uint(x_s[ar * 36 + kb + (lane & 3) + 4]);
                a[mt][3] = __float_as_uint(x_s[(ar + 8) * 36 + kb + (lane & 3) + 4]);
            }
            #pragma unroll
            for (int nt = 0; nt < 4; nt++) {
                int bc = wn * 32 + nt * 8 + (lane >> 2);
                uint32_t b0 = __float_as_uint(w_s[(kb + (lane & 3)) * 72 + bc]);
                uint32_t b1 = __float_as_uint(w_s[(kb + (lane & 3) + 4) * 72 + bc]);
                mma8(acc[0][nt], a[0][0], a[0][1], a[0][2], a[0][3], b0, b1);
                mma8(acc[1][nt], a[1][0], a[1][1], a[1][2], a[1][3], b0, b1);
            }
        }
        __syncthreads();
    }

    // epilogue: add bias, scatter to g_xw[t][n][g]; row R = n*T + t
    #pragma unroll
    for (int nt = 0; nt < 4; nt++) {
        int lc = wn * 32 + nt * 8 + ((lane & 3) << 1);
        float bs0 = __ldg(bx + jc0 + lc) + __ldg(bh + jc0 + lc);
        float bs1 = __ldg(bx + jc0 + lc + 1) + __ldg(bh + jc0 + lc + 1);
        #pragma unroll
        for (int mt = 0; mt < 2; mt++) {
            int R1 = row0 + wm * 32 + mt * 16 + (lane >> 2);
            int R2 = R1 + 8;
            int t1 = R1 & (TT - 1), n1 = R1 >> 9;
            int t2 = R2 & (TT - 1), n2 = R2 >> 9;
            *(float2*)(g_xw + (size_t)t1 * (NB * GG) + n1 * GG + gc0 + lc) =
                make_float2(acc[mt][nt][0] + bs0, acc[mt][nt][1] + bs1);
            *(float2*)(g_xw + (size_t)t2 * (NB * GG) + n2 * GG + gc0 + lc) =
                make_float2(acc[mt][nt][2] + bs0, acc[mt][nt][3] + bs1);
        }
    }
}

// ================= Phase 2: persistent recurrence ==========================
#define HS_STRIDE 260
#define WH_STRIDE 136
#define REC_SMEM ((32 * HS_STRIDE + 256 * WH_STRIDE) * 4)

__global__ void __launch_bounds__(256, 1) lstm_rec_kernel(
    const float* __restrict__ w_hi, const float* __restrict__ w_hf,
    const float* __restrict__ w_hg, const float* __restrict__ w_ho,
    float* __restrict__ out, int out_n)
{
    extern __shared__ float sm[];
    float* h_s  = sm;                   // [32][260]
    float* wh_s = sm + 32 * HS_STRIDE;  // [256][136]

    const int tid = threadIdx.x, lane = tid & 31, warp = tid >> 5;
    const int wm = warp >> 2, wj = warp & 3;
    const int bn = blockIdx.x >> 3, bj = blockIdx.x & 7;
    const int nBase = bn * 32, j0 = bj * 32;

    for (int q = tid; q < 8192; q += 256) {
        int k = q >> 5, cc4 = q & 31, gt = cc4 >> 3, jj = (cc4 & 7) << 2;
        const float* src = (gt == 0) ? w_hi : (gt == 1) ? w_hf : (gt == 2) ? w_hg : w_ho;
        float4 v = *(const float4*)(src + (size_t)k * 256 + j0 + jj);
        v.x = cvt_tf32(v.x); v.y = cvt_tf32(v.y);
        v.z = cvt_tf32(v.z); v.w = cvt_tf32(v.w);
        *(float4*)(wh_s + k * WH_STRIDE + gt * 32 + jj) = v;
    }

    const int rA = wm * 16 + (lane >> 2);
    const int n1 = nBase + rA;
    const int c2 = wj * 8 + ((lane & 3) << 1);
    const int jA = j0 + c2;
    const int aoff0 = rA * HS_STRIDE + (lane & 3);
    const int aoff1 = aoff0 + 8 * HS_STRIDE;
    int boff[4];
    #pragma unroll
    for (int gt = 0; gt < 4; gt++)
        boff[gt] = (lane & 3) * WH_STRIDE + gt * 32 + wj * 8 + (lane >> 2);

    float cst[4] = {0.f, 0.f, 0.f, 0.f};

    for (int t = 0; t < TT; t++) {
        const float* xw = g_xw + (size_t)t * (NB * GG);
        float2 xv[4][2];
        #pragma unroll
        for (int gt = 0; gt < 4; gt++) {
            int col = gt * 256 + jA;
            xv[gt][0] = *(const float2*)(xw + (size_t)n1 * GG + col);
            xv[gt][1] = *(const float2*)(xw + (size_t)(n1 + 8) * GG + col);
        }

        const float* hsrc = g_h + (t & 1) * (NB * HH) + nBase * HH;
        #pragma unroll
        for (int i = 0; i < 8; i++) {
            int q = i * 256 + tid, row = q >> 6, c4 = (q & 63) << 2;
            float4 v = __ldcg((const float4*)(hsrc + row * HH + c4));
            float* d = h_s + row * HS_STRIDE + c4;
            d[0] = cvt_tf32(v.x); d[1] = cvt_tf32(v.y);
            d[2] = cvt_tf32(v.z); d[3] = cvt_tf32(v.w);
        }
        __syncthreads();

        float acc[4][4];
        #pragma unroll
        for (int gt = 0; gt < 4; gt++) {
            acc[gt][0] = xv[gt][0].x; acc[gt][1] = xv[gt][0].y;
            acc[gt][2] = xv[gt][1].x; acc[gt][3] = xv[gt][1].y;
        }

        #pragma unroll
        for (int kc = 0; kc < 32; kc++) {
            const int k0 = kc * 8;
            uint32_t a0 = __float_as_uint(h_s[aoff0 + k0]);
            uint32_t a1 = __float_as_uint(h_s[aoff1 + k0]);
            uint32_t a2 = __float_as_uint(h_s[aoff0 + k0 + 4]);
            uint32_t a3 = __float_as_uint(h_s[aoff1 + k0 + 4]);
            #pragma unroll
            for (int gt = 0; gt < 4; gt++) {
                uint32_t b0 = __float_as_uint(wh_s[boff[gt] + k0 * WH_STRIDE]);
                uint32_t b1 = __float_as_uint(wh_s[boff[gt] + (k0 + 4) * WH_STRIDE]);
                mma8(acc[gt], a0, a1, a2, a3, b0, b1);
            }
        }

        float hv[4];
        #pragma unroll
        for (int p = 0; p < 4; p++) {
            float ig = sigm(acc[0][p]);
            float fg = sigm(acc[1][p]);
            float gg = tanh_acc(acc[2][p]);
            float og = sigm(acc[3][p]);
            float c = fg * cst[p] + ig * gg;
            cst[p] = c;
            hv[p] = og * tanh_acc(c);
        }

        if (t < TT - 1) {
            float* hdst = g_h + ((t + 1) & 1) * (NB * HH);
            __stcg((float2*)(hdst + n1 * HH + jA), make_float2(hv[0], hv[1]));
            __stcg((float2*)(hdst + (n1 + 8) * HH + jA), make_float2(hv[2], hv[3]));
            __threadfence();
            __syncthreads();
            if (tid == 0) {
                unsigned target = gridDim.x * (unsigned)(t + 1);
                atomicAdd(&g_bar, 1u);
                while (*(volatile unsigned*)&g_bar < target) { }
            }
            __syncthreads();
        } else {
            *(float2*)(out + n1 * HH + jA) = make_float2(hv[0], hv[1]);
            *(float2*)(out + (n1 + 8) * HH + jA) = make_float2(hv[2], hv[3]);
            if (out_n >= 2 * NB * HH) {
                *(float2*)(out + NB * HH + n1 * HH + jA) = make_float2(cst[0], cst[1]);
                *(float2*)(out + NB * HH + (n1 + 8) * HH + jA) = make_float2(cst[2], cst[3]);
            }
        }
    }
}

// ================= launch ==================================================
extern "C" void kernel_launch(void* const* d_in, const int* in_sizes, int n_in,
                              void* d_out, int out_size) {
    const float* x    = (const float*)d_in[0];
    const float* w_ii = (const float*)d_in[1];
    const float* w_hi = (const float*)d_in[2];
    const float* w_if = (const float*)d_in[3];
    const float* w_hf = (const float*)d_in[4];
    const float* w_ig = (const float*)d_in[5];
    const float* w_hg = (const float*)d_in[6];
    const float* w_io = (const float*)d_in[7];
    const float* w_ho = (const float*)d_in[8];
    const float* b_ii = (const float*)d_in[9];
    const float* b_hi = (const float*)d_in[10];
    const float* b_if = (const float*)d_in[11];
    const float* b_hf = (const float*)d_in[12];
    const float* b_ig = (const float*)d_in[13];
    const float* b_hg = (const float*)d_in[14];
    const float* b_io = (const float*)d_in[15];
    const float* b_ho = (const float*)d_in[16];
    float* out = (float*)d_out;

    void* hAddr = nullptr; void* barAddr = nullptr;
    cudaGetSymbolAddress(&hAddr, g_h);
    cudaGetSymbolAddress(&barAddr, g_bar);
    cudaMemsetAsync(hAddr, 0, (size_t)NB * HH * sizeof(float), 0);
    cudaMemsetAsync(barAddr, 0, sizeof(unsigned), 0);

    dim3 g1(16, 1024);
    lstm_xw_kernel<<<g1, 256>>>(x, w_ii, w_if, w_ig, w_io,
                                b_ii, b_hi, b_if, b_hf, b_ig, b_hg, b_io, b_ho);

    static int smem_set = 0;
    if (!smem_set) {
        cudaFuncSetAttribute(lstm_rec_kernel,
                             cudaFuncAttributeMaxDynamicSharedMemorySize, REC_SMEM);
        smem_set = 1;
    }
    lstm_rec_kernel<<<64, 256, REC_SMEM>>>(w_hi, w_hf, w_hg, w_ho, out, out_size);
}

// round 3
// speedup vs baseline: 1.1608x; 1.1608x over previous
#include <cuda_runtime.h>
#include <stdint.h>

#define TT 512
#define NB 256
#define HH 256
#define GG 1024

__device__ float    g_xw[(size_t)TT * NB * GG];
__device__ float    g_h[2 * NB * HH];
__device__ unsigned g_bars[8 * 32];   // one counter per batch-group, 128B apart

__device__ __forceinline__ float cvt_tf32(float x) {
    float r; asm("cvt.rna.tf32.f32 %0, %1;" : "=f"(r) : "f"(x)); return r;
}
__device__ __forceinline__ void mma8(float d[4], uint32_t a0, uint32_t a1,
                                     uint32_t a2, uint32_t a3, uint32_t b0, uint32_t b1) {
    asm volatile("mma.sync.aligned.m16n8k8.row.col.f32.tf32.tf32.f32 "
                 "{%0,%1,%2,%3}, {%4,%5,%6,%7}, {%8,%9}, {%0,%1,%2,%3};\n"
                 : "+f"(d[0]), "+f"(d[1]), "+f"(d[2]), "+f"(d[3])
                 : "r"(a0), "r"(a1), "r"(a2), "r"(a3), "r"(b0), "r"(b1));
}
__device__ __forceinline__ float sigm(float x) { return __fdividef(1.f, 1.f + __expf(-x)); }
__device__ __forceinline__ float tanh_acc(float x) { return 1.f - __fdividef(2.f, __expf(2.f * x) + 1.f); }

// ================= Phase 1: xW = x @ [Wi|Wf|Wg|Wo] + b (unchanged) ========
__global__ void __launch_bounds__(256) lstm_xw_kernel(
    const float* __restrict__ x,
    const float* __restrict__ w0, const float* __restrict__ w1,
    const float* __restrict__ w2, const float* __restrict__ w3,
    const float* __restrict__ bx0, const float* __restrict__ bh0,
    const float* __restrict__ bx1, const float* __restrict__ bh1,
    const float* __restrict__ bx2, const float* __restrict__ bh2,
    const float* __restrict__ bx3, const float* __restrict__ bh3)
{
    __shared__ float x_s[128 * 36];
    __shared__ float w_s[32 * 72];

    const int tid = threadIdx.x, lane = tid & 31, warp = tid >> 5;
    const int wm = warp >> 1, wn = warp & 1;
    const int row0 = blockIdx.y * 128;
    const int gc0 = blockIdx.x * 64;
    const int gate = gc0 >> 8, jc0 = gc0 & 255;

    const float* wx = (gate == 0) ? w0 : (gate == 1) ? w1 : (gate == 2) ? w2 : w3;
    const float* bx = (gate == 0) ? bx0 : (gate == 1) ? bx1 : (gate == 2) ? bx2 : bx3;
    const float* bh = (gate == 0) ? bh0 : (gate == 1) ? bh1 : (gate == 2) ? bh2 : bh3;

    float acc[2][4][4];
    #pragma unroll
    for (int i = 0; i < 2; i++)
        #pragma unroll
        for (int j = 0; j < 4; j++)
            #pragma unroll
            for (int k = 0; k < 4; k++) acc[i][j][k] = 0.f;

    for (int k0 = 0; k0 < 256; k0 += 32) {
        #pragma unroll
        for (int i = 0; i < 4; i++) {
            int q = i * 256 + tid, r = q >> 3, c4 = (q & 7) << 2;
            float4 v = *(const float4*)(x + (size_t)(row0 + r) * 256 + k0 + c4);
            float* d = x_s + r * 36 + c4;
            d[0] = cvt_tf32(v.x); d[1] = cvt_tf32(v.y);
            d[2] = cvt_tf32(v.z); d[3] = cvt_tf32(v.w);
        }
        #pragma unroll
        for (int i = 0; i < 2; i++) {
            int q = i * 256 + tid, r = q >> 4, c4 = (q & 15) << 2;
            float4 v = *(const float4*)(wx + (size_t)(k0 + r) * 256 + jc0 + c4);
            v.x = cvt_tf32(v.x); v.y = cvt_tf32(v.y);
            v.z = cvt_tf32(v.z); v.w = cvt_tf32(v.w);
            *(float4*)(w_s + r * 72 + c4) = v;
        }
        __syncthreads();
        #pragma unroll
        for (int kk = 0; kk < 4; kk++) {
            const int kb = kk * 8;
            uint32_t a[2][4];
            #pragma unroll
            for (int mt = 0; mt < 2; mt++) {
                int ar = wm * 32 + mt * 16 + (lane >> 2);
                a[mt][0] = __float_as_uint(x_s[ar * 36 + kb + (lane & 3)]);
                a[mt][1] = __float_as_uint(x_s[(ar + 8) * 36 + kb + (lane & 3)]);
                a[mt][2] = __float_as_uint(x_s[ar * 36 + kb + (lane & 3) + 4]);
                a[mt][3] = __float_as_uint(x_s[(ar + 8) * 36 + kb + (lane & 3) + 4]);
            }
            #pragma unroll
            for (int nt = 0; nt < 4; nt++) {
                int bc = wn * 32 + nt * 8 + (lane >> 2);
                uint32_t b0 = __float_as_uint(w_s[(kb + (lane & 3)) * 72 + bc]);
                uint32_t b1 = __float_as_uint(w_s[(kb + (lane & 3) + 4) * 72 + bc]);
                mma8(acc[0][nt], a[0][0], a[0][1], a[0][2], a[0][3], b0, b1);
                mma8(acc[1][nt], a[1][0], a[1][1], a[1][2], a[1][3], b0, b1);
            }
        }
        __syncthreads();
    }

    #pragma unroll
    for (int nt = 0; nt < 4; nt++) {
        int lc = wn * 32 + nt * 8 + ((lane & 3) << 1);
        float bs0 = __ldg(bx + jc0 + lc) + __ldg(bh + jc0 + lc);
        float bs1 = __ldg(bx + jc0 + lc + 1) + __ldg(bh + jc0 + lc + 1);
        #pragma unroll
        for (int mt = 0; mt < 2; mt++) {
            int R1 = row0 + wm * 32 + mt * 16 + (lane >> 2);
            int R2 = R1 + 8;
            int t1 = R1 & (TT - 1), n1 = R1 >> 9;
            int t2 = R2 & (TT - 1), n2 = R2 >> 9;
            *(float2*)(g_xw + (size_t)t1 * (NB * GG) + n1 * GG + gc0 + lc) =
                make_float2(acc[mt][nt][0] + bs0, acc[mt][nt][1] + bs1);
            *(float2*)(g_xw + (size_t)t2 * (NB * GG) + n2 * GG + gc0 + lc) =
                make_float2(acc[mt][nt][2] + bs0, acc[mt][nt][3] + bs1);
        }
    }
}

// ================= Phase 2: persistent recurrence, B in registers =========
// 128 CTAs: bn = blk>>4 (batch group of 32), bj = blk&15 (16 hidden cols).
// 8 warps: wm = warp&1 (row half), wc = warp>>1 (4 hidden cols).
// Warp tile: 16 rows x 16 virtual cols, v = jj*4 + gt.
#define HS 268   // h_s row stride (floats); 268 % 32 = 12 -> conflict-free frags

__global__ void __launch_bounds__(256, 1) lstm_rec_kernel(
    const float* __restrict__ w_hi, const float* __restrict__ w_hf,
    const float* __restrict__ w_hg, const float* __restrict__ w_ho,
    float* __restrict__ out, int out_n)
{
    __shared__ float h_s[32 * HS];

    const int tid = threadIdx.x, lane = tid & 31, warp = tid >> 5;
    const int wm = warp & 1, wc = warp >> 1;
    const int bn = blockIdx.x >> 4, bj = blockIdx.x & 15;
    const int nBase = bn * 32, j0 = bj * 16;
    const int jw = j0 + wc * 4;
    const int u = lane >> 2, r = lane & 3;
    const int rA = wm * 16 + u;              // local row for c0,c1; c2,c3 = rA+8

    volatile unsigned* bar = &g_bars[bn * 32];

    // ---- load B (Wh slice) into registers: b0/b1[kc][nt] ----
    float b0[32][2], b1[32][2];
    #pragma unroll
    for (int nt = 0; nt < 2; nt++) {
        int v = nt * 8 + u;                  // virtual col 0..15
        int jj = v >> 2, gt = v & 3;
        const float* w = (gt == 0) ? w_hi : (gt == 1) ? w_hf : (gt == 2) ? w_hg : w_ho;
        const float* wp = w + (jw + jj);
        #pragma unroll
        for (int kc = 0; kc < 32; kc++) {
            int k = kc * 8 + r;
            b0[kc][nt] = cvt_tf32(__ldg(wp + k * 256));
            b1[kc][nt] = cvt_tf32(__ldg(wp + (k + 4) * 256));
        }
    }

    // per-lane xw/gather coordinates (lane-constant)
    int gcol[2][2], xrow0, xrow1;
    #pragma unroll
    for (int nt = 0; nt < 2; nt++)
        #pragma unroll
        for (int cc = 0; cc < 2; cc++) {
            int v = nt * 8 + 2 * r + cc;
            gcol[nt][cc] = (v & 3) * 256 + jw + (v >> 2);
        }
    xrow0 = (nBase + rA) * GG;
    xrow1 = (nBase + rA + 8) * GG;

    // epilogue cell coordinates: this lane owns row rA (even lane) / rA+8 (odd)
    const int odd = lane & 1;
    const int myrow = nBase + rA + (odd ? 8 : 0);
    int mycol[2];
    #pragma unroll
    for (int nt = 0; nt < 2; nt++) mycol[nt] = jw + nt * 2 + (r >> 1);

    float cst[2] = {0.f, 0.f};

    for (int t = 0; t < TT; t++) {
        // xw gather — independent of h, issue before the wait
        const float* xw = g_xw + (size_t)t * (NB * GG);
        float acc[2][4];
        #pragma unroll
        for (int nt = 0; nt < 2; nt++) {
            acc[nt][0] = __ldg(xw + xrow0 + gcol[nt][0]);
            acc[nt][1] = __ldg(xw + xrow0 + gcol[nt][1]);
            acc[nt][2] = __ldg(xw + xrow1 + gcol[nt][0]);
            acc[nt][3] = __ldg(xw + xrow1 + gcol[nt][1]);
        }

        if (t > 0) {
            __syncthreads();                 // prior-step LDS done before spin/STS
            if (tid == 0) {
                unsigned target = 16u * (unsigned)t;
                while (*bar < target) { }
                __threadfence();
            }
            __syncthreads();
        }

        // stage h tile (32 x 256) into smem, tf32-converted
        const float* hsrc = g_h + (t & 1) * (NB * HH) + nBase * HH;
        #pragma unroll
        for (int i = 0; i < 8; i++) {
            int f = i * 256 + tid, row = f >> 6, c4 = (f & 63) << 2;
            float4 v = __ldcg((const float4*)(hsrc + row * HH + c4));
            v.x = cvt_tf32(v.x); v.y = cvt_tf32(v.y);
            v.z = cvt_tf32(v.z); v.w = cvt_tf32(v.w);
            *(float4*)(h_s + row * HS + c4) = v;
        }
        __syncthreads();

        // mainloop: A from smem, B from registers
        const int a0base = rA * HS + r;
        const int a1base = (rA + 8) * HS + r;
        #pragma unroll
        for (int kc = 0; kc < 32; kc++) {
            const int k0 = kc * 8;
            uint32_t a0 = __float_as_uint(h_s[a0base + k0]);
            uint32_t a1 = __float_as_uint(h_s[a1base + k0]);
            uint32_t a2 = __float_as_uint(h_s[a0base + k0 + 4]);
            uint32_t a3 = __float_as_uint(h_s[a1base + k0 + 4]);
            mma8(acc[0], a0, a1, a2, a3, __float_as_uint(b0[kc][0]), __float_as_uint(b1[kc][0]));
            mma8(acc[1], a0, a1, a2, a3, __float_as_uint(b0[kc][1]), __float_as_uint(b1[kc][1]));
        }

        // epilogue: lane-pair gate exchange + cell update
        float hv[2];
        #pragma unroll
        for (int nt = 0; nt < 2; nt++) {
            // even lane holds (i,f) rows rA & rA+8; odd holds (g,o) rows rA & rA+8
            float s0 = odd ? acc[nt][0] : acc[nt][2];
            float s1 = odd ? acc[nt][1] : acc[nt][3];
            float r0 = __shfl_xor_sync(0xFFFFFFFFu, s0, 1);
            float r1 = __shfl_xor_sync(0xFFFFFFFFu, s1, 1);
            float iv, fv, gv, ov;
            if (odd) { iv = r0; fv = r1; gv = acc[nt][2]; ov = acc[nt][3]; }
            else     { iv = acc[nt][0]; fv = acc[nt][1]; gv = r0; ov = r1; }
            float ig = sigm(iv), fg = sigm(fv), gg = tanh_acc(gv), og = sigm(ov);
            float c = fg * cst[nt] + ig * gg;
            cst[nt] = c;
            hv[nt] = og * tanh_acc(c);
        }

        if (t < TT - 1) {
            float* hdst = g_h + ((t + 1) & 1) * (NB * HH) + myrow * HH;
            __stcg(hdst + mycol[0], hv[0]);
            __stcg(hdst + mycol[1], hv[1]);
            __threadfence();
            __syncthreads();
            if (tid == 0) atomicAdd((unsigned*)bar, 1u);
        } else {
            out[myrow * HH + mycol[0]] = hv[0];
            out[myrow * HH + mycol[1]] = hv[1];
            if (out_n >= 2 * NB * HH) {
                out[NB * HH + myrow * HH + mycol[0]] = cst[0];
                out[NB * HH + myrow * HH + mycol[1]] = cst[1];
            }
        }
    }
}

// ================= launch ==================================================
extern "C" void kernel_launch(void* const* d_in, const int* in_sizes, int n_in,
                              void* d_out, int out_size) {
    const float* x    = (const float*)d_in[0];
    const float* w_ii = (const float*)d_in[1];
    const float* w_hi = (const float*)d_in[2];
    const float* w_if = (const float*)d_in[3];
    const float* w_hf = (const float*)d_in[4];
    const float* w_ig = (const float*)d_in[5];
    const float* w_hg = (const float*)d_in[6];
    const float* w_io = (const float*)d_in[7];
    const float* w_ho = (const float*)d_in[8];
    const float* b_ii = (const float*)d_in[9];
    const float* b_hi = (const float*)d_in[10];
    const float* b_if = (const float*)d_in[11];
    const float* b_hf = (const float*)d_in[12];
    const float* b_ig = (const float*)d_in[13];
    const float* b_hg = (const float*)d_in[14];
    const float* b_io = (const float*)d_in[15];
    const float* b_ho = (const float*)d_in[16];
    float* out = (float*)d_out;

    void* hAddr = nullptr; void* barAddr = nullptr;
    cudaGetSymbolAddress(&hAddr, g_h);
    cudaGetSymbolAddress(&barAddr, g_bars);
    cudaMemsetAsync(hAddr, 0, (size_t)NB * HH * sizeof(float), 0);
    cudaMemsetAsync(barAddr, 0, 8 * 32 * sizeof(unsigned), 0);

    dim3 g1(16, 1024);
    lstm_xw_kernel<<<g1, 256>>>(x, w_ii, w_if, w_ig, w_io,
                                b_ii, b_hi, b_if, b_hf, b_ig, b_hg, b_io, b_ho);

    lstm_rec_kernel<<<128, 256>>>(w_hi, w_hf, w_hg, w_ho, out, out_size);
}

// round 4
// speedup vs baseline: 1.3747x; 1.1843x over previous
#include <cuda_runtime.h>
#include <stdint.h>

#define TT 512
#define NB 256
#define HH 256
#define GG 1024

__device__ float    g_xw[(size_t)TT * NB * GG];
__device__ float    g_h[2 * NB * HH];
__device__ unsigned g_bars[8 * 32];   // one counter per batch-group, 128B apart

__device__ __forceinline__ float cvt_tf32(float x) {
    float r; asm("cvt.rna.tf32.f32 %0, %1;" : "=f"(r) : "f"(x)); return r;
}
__device__ __forceinline__ void mma8(float d[4], uint32_t a0, uint32_t a1,
                                     uint32_t a2, uint32_t a3, uint32_t b0, uint32_t b1) {
    asm volatile("mma.sync.aligned.m16n8k8.row.col.f32.tf32.tf32.f32 "
                 "{%0,%1,%2,%3}, {%4,%5,%6,%7}, {%8,%9}, {%0,%1,%2,%3};\n"
                 : "+f"(d[0]), "+f"(d[1]), "+f"(d[2]), "+f"(d[3])
                 : "r"(a0), "r"(a1), "r"(a2), "r"(a3), "r"(b0), "r"(b1));
}
__device__ __forceinline__ float sigm(float x) { return __fdividef(1.f, 1.f + __expf(-x)); }
__device__ __forceinline__ float tanh_acc(float x) { return 1.f - __fdividef(2.f, __expf(2.f * x) + 1.f); }
__device__ __forceinline__ unsigned ld_acq(const unsigned* p) {
    unsigned v; asm volatile("ld.acquire.gpu.global.u32 %0, [%1];" : "=r"(v) : "l"(p)); return v;
}
__device__ __forceinline__ void red_rel(unsigned* p, unsigned v) {
    asm volatile("red.release.gpu.global.add.u32 [%0], %1;" :: "l"(p), "r"(v) : "memory");
}

// ================= Phase 1: xW = x @ [Wi|Wf|Wg|Wo] + b ====================
__global__ void __launch_bounds__(256) lstm_xw_kernel(
    const float* __restrict__ x,
    const float* __restrict__ w0, const float* __restrict__ w1,
    const float* __restrict__ w2, const float* __restrict__ w3,
    const float* __restrict__ bx0, const float* __restrict__ bh0,
    const float* __restrict__ bx1, const float* __restrict__ bh1,
    const float* __restrict__ bx2, const float* __restrict__ bh2,
    const float* __restrict__ bx3, const float* __restrict__ bh3)
{
    __shared__ float x_s[128 * 36];
    __shared__ float w_s[32 * 72];

    const int tid = threadIdx.x, lane = tid & 31, warp = tid >> 5;
    const int wm = warp >> 1, wn = warp & 1;
    const int row0 = blockIdx.y * 128;
    const int gc0 = blockIdx.x * 64;
    const int gate = gc0 >> 8, jc0 = gc0 & 255;

    const float* wx = (gate == 0) ? w0 : (gate == 1) ? w1 : (gate == 2) ? w2 : w3;
    const float* bx = (gate == 0) ? bx0 : (gate == 1) ? bx1 : (gate == 2) ? bx2 : bx3;
    const float* bh = (gate == 0) ? bh0 : (gate == 1) ? bh1 : (gate == 2) ? bh2 : bh3;

    float acc[2][4][4];
    #pragma unroll
    for (int i = 0; i < 2; i++)
        #pragma unroll
        for (int j = 0; j < 4; j++)
            #pragma unroll
            for (int k = 0; k < 4; k++) acc[i][j][k] = 0.f;

    for (int k0 = 0; k0 < 256; k0 += 32) {
        #pragma unroll
        for (int i = 0; i < 4; i++) {
            int q = i * 256 + tid, r = q >> 3, c4 = (q & 7) << 2;
            float4 v = *(const float4*)(x + (size_t)(row0 + r) * 256 + k0 + c4);
            float* d = x_s + r * 36 + c4;
            d[0] = cvt_tf32(v.x); d[1] = cvt_tf32(v.y);
            d[2] = cvt_tf32(v.z); d[3] = cvt_tf32(v.w);
        }
        #pragma unroll
        for (int i = 0; i < 2; i++) {
            int q = i * 256 + tid, r = q >> 4, c4 = (q & 15) << 2;
            float4 v = *(const float4*)(wx + (size_t)(k0 + r) * 256 + jc0 + c4);
            v.x = cvt_tf32(v.x); v.y = cvt_tf32(v.y);
            v.z = cvt_tf32(v.z); v.w = cvt_tf32(v.w);
            *(float4*)(w_s + r * 72 + c4) = v;
        }
        __syncthreads();
        #pragma unroll
        for (int kk = 0; kk < 4; kk++) {
            const int kb = kk * 8;
            uint32_t a[2][4];
            #pragma unroll
            for (int mt = 0; mt < 2; mt++) {
                int ar = wm * 32 + mt * 16 + (lane >> 2);
                a[mt][0] = __float_as_uint(x_s[ar * 36 + kb + (lane & 3)]);
                a[mt][1] = __float_as_uint(x_s[(ar + 8) * 36 + kb + (lane & 3)]);
                a[mt][2] = __float_as_uint(x_s[ar * 36 + kb + (lane & 3) + 4]);
                a[mt][3] = __float_as_uint(x_s[(ar + 8) * 36 + kb + (lane & 3) + 4]);
            }
            #pragma unroll
            for (int nt = 0; nt < 4; nt++) {
                int bc = wn * 32 + nt * 8 + (lane >> 2);
                uint32_t b0 = __float_as_uint(w_s[(kb + (lane & 3)) * 72 + bc]);
                uint32_t b1 = __float_as_uint(w_s[(kb + (lane & 3) + 4) * 72 + bc]);
                mma8(acc[0][nt], a[0][0], a[0][1], a[0][2], a[0][3], b0, b1);
                mma8(acc[1][nt], a[1][0], a[1][1], a[1][2], a[1][3], b0, b1);
            }
        }
        __syncthreads();
    }

    // ---- epilogue: stage through smem, write full 32B sectors ----
    float* ebuf = x_s;   // 128 x 18 floats, reuse (last x_s read was before final sync)
    #pragma unroll
    for (int p = 0; p < 4; p++) {
        int jcol = jc0 + wn * 32 + p * 8 + ((lane & 3) << 1);
        float bs0 = __ldg(bx + jcol)     + __ldg(bh + jcol);
        float bs1 = __ldg(bx + jcol + 1) + __ldg(bh + jcol + 1);
        #pragma unroll
        for (int mt = 0; mt < 2; mt++) {
            int lr = wm * 32 + mt * 16 + (lane >> 2);
            int lc = wn * 8 + ((lane & 3) << 1);
            ebuf[lr * 18 + lc]           = acc[mt][p][0] + bs0;
            ebuf[lr * 18 + lc + 1]       = acc[mt][p][1] + bs1;
            ebuf[(lr + 8) * 18 + lc]     = acc[mt][p][2] + bs0;
            ebuf[(lr + 8) * 18 + lc + 1] = acc[mt][p][3] + bs1;
        }
        __syncthreads();
        #pragma unroll
        for (int it = 0; it < 8; it++) {
            int row  = warp * 16 + it * 2 + (lane >> 4);
            int sc   = (lane >> 3) & 1;
            int col8 = lane & 7;
            int R = row0 + row;
            int t = R & (TT - 1), n = R >> 9;
            g_xw[(size_t)t * (NB * GG) + n * GG + gc0 + sc * 32 + p * 8 + col8] =
                ebuf[row * 18 + sc * 8 + col8];
        }
        __syncthreads();
    }
}

// ================= Phase 2: persistent recurrence ==========================
// 128 CTAs: bn = blk>>4 (32-batch group), bj = blk&15 (16 hidden cols).
// 8 warps: wm = warp&1 (row half), wc = warp>>1 (4 hidden cols).
// Warp tile: 16 rows x 16 virtual cols, v = jj*4 + gt. B in registers.
#define HS 268   // h_s row stride
#define XS 68    // xw_s row stride (per batch row: 4 gates x 16 cols + pad)

__global__ void __launch_bounds__(256, 1) lstm_rec_kernel(
    const float* __restrict__ w_hi, const float* __restrict__ w_hf,
    const float* __restrict__ w_hg, const float* __restrict__ w_ho,
    float* __restrict__ out, int out_n)
{
    __shared__ float h_s[32 * HS];
    __shared__ float xw_s[32 * XS];

    const int tid = threadIdx.x, lane = tid & 31, warp = tid >> 5;
    const int wm = warp & 1, wc = warp >> 1;
    const int bn = blockIdx.x >> 4, bj = blockIdx.x & 15;
    const int nBase = bn * 32, j0 = bj * 16;
    const int jw = j0 + wc * 4;
    const int u = lane >> 2, r = lane & 3;
    const int rA = wm * 16 + u;

    unsigned* bar = &g_bars[bn * 32];

    // ---- B (Wh slice) into registers ----
    float b0[32][2], b1[32][2];
    #pragma unroll
    for (int nt = 0; nt < 2; nt++) {
        int v = nt * 8 + u;
        int jj = v >> 2, gt = v & 3;
        const float* w = (gt == 0) ? w_hi : (gt == 1) ? w_hf : (gt == 2) ? w_hg : w_ho;
        const float* wp = w + (jw + jj);
        #pragma unroll
        for (int kc = 0; kc < 32; kc++) {
            int k = kc * 8 + r;
            b0[kc][nt] = cvt_tf32(__ldg(wp + k * 256));
            b1[kc][nt] = cvt_tf32(__ldg(wp + (k + 4) * 256));
        }
    }

    // fragment-init LDS offsets (lane-constant)
    int ioff[2][4];
    #pragma unroll
    for (int nt = 0; nt < 2; nt++)
        #pragma unroll
        for (int sl = 0; sl < 4; sl++) {
            int cc = sl & 1, half = sl >> 1;
            int v = nt * 8 + 2 * r + cc;
            ioff[nt][sl] = (rA + half * 8) * XS + (v & 3) * 16 + wc * 4 + (v >> 2);
        }

    // epilogue cell coordinates
    const int odd = lane & 1;
    const int myrow = nBase + rA + (odd ? 8 : 0);
    int mycol[2];
    #pragma unroll
    for (int nt = 0; nt < 2; nt++) mycol[nt] = jw + nt * 2 + (r >> 1);

    float cst[2] = {0.f, 0.f};

    for (int t = 0; t < TT; t++) {
        // ---- coalesced xw chunk load (independent of h): 2 x LDG.128 ----
        const float* xwb = g_xw + (size_t)t * (NB * GG) + (size_t)nBase * GG + j0;
        float4 xv[2];
        #pragma unroll
        for (int p = 0; p < 2; p++) {
            int f = p * 256 + tid, seg = f >> 2, w4 = f & 3;
            int row = seg >> 2, gt = seg & 3;
            xv[p] = __ldg((const float4*)(xwb + (size_t)row * GG + gt * 256 + w4 * 4));
        }

        if (t > 0) {
            if (tid == 0) {
                unsigned target = 16u * (unsigned)t;
                while (ld_acq(bar) < target) { }
            }
            __syncthreads();
            // stage h tile
            const float* hsrc = g_h + (t & 1) * (NB * HH) + nBase * HH;
            #pragma unroll
            for (int i = 0; i < 8; i++) {
                int f = i * 256 + tid, row = f >> 6, c4 = (f & 63) << 2;
                float4 v = __ldcg((const float4*)(hsrc + row * HH + c4));
                v.x = cvt_tf32(v.x); v.y = cvt_tf32(v.y);
                v.z = cvt_tf32(v.z); v.w = cvt_tf32(v.w);
                *(float4*)(h_s + row * HS + c4) = v;
            }
        }
        // stage xw chunk
        #pragma unroll
        for (int p = 0; p < 2; p++) {
            int f = p * 256 + tid, seg = f >> 2, w4 = f & 3;
            int row = seg >> 2, gt = seg & 3;
            *(float4*)(xw_s + row * XS + gt * 16 + w4 * 4) = xv[p];
        }
        __syncthreads();

        // accumulator init from staged xw
        float acc[2][4];
        #pragma unroll
        for (int nt = 0; nt < 2; nt++)
            #pragma unroll
            for (int sl = 0; sl < 4; sl++)
                acc[nt][sl] = xw_s[ioff[nt][sl]];

        if (t > 0) {
            const int a0base = rA * HS + r;
            const int a1base = (rA + 8) * HS + r;
            #pragma unroll
            for (int kc = 0; kc < 32; kc++) {
                const int k0 = kc * 8;
                uint32_t a0 = __float_as_uint(h_s[a0base + k0]);
                uint32_t a1 = __float_as_uint(h_s[a1base + k0]);
                uint32_t a2 = __float_as_uint(h_s[a0base + k0 + 4]);
                uint32_t a3 = __float_as_uint(h_s[a1base + k0 + 4]);
                mma8(acc[0], a0, a1, a2, a3, __float_as_uint(b0[kc][0]), __float_as_uint(b1[kc][0]));
                mma8(acc[1], a0, a1, a2, a3, __float_as_uint(b0[kc][1]), __float_as_uint(b1[kc][1]));
            }
        }

        // ---- epilogue: lane-pair gate exchange + cell update ----
        float hv[2];
        #pragma unroll
        for (int nt = 0; nt < 2; nt++) {
            float s0 = odd ? acc[nt][0] : acc[nt][2];
            float s1 = odd ? acc[nt][1] : acc[nt][3];
            float r0 = __shfl_xor_sync(0xFFFFFFFFu, s0, 1);
            float r1 = __shfl_xor_sync(0xFFFFFFFFu, s1, 1);
            float iv, fv, gv, ov;
            if (odd) { iv = r0; fv = r1; gv = acc[nt][2]; ov = acc[nt][3]; }
            else     { iv = acc[nt][0]; fv = acc[nt][1]; gv = r0; ov = r1; }
            float ig = sigm(iv), fg = sigm(fv), gg = tanh_acc(gv), og = sigm(ov);
            float c = fg * cst[nt] + ig * gg;
            cst[nt] = c;
            hv[nt] = og * tanh_acc(c);
        }

        if (t < TT - 1) {
            float* hdst = g_h + ((t + 1) & 1) * (NB * HH) + myrow * HH;
            __stcg(hdst + mycol[0], hv[0]);
            __stcg(hdst + mycol[1], hv[1]);
            __syncthreads();
            if (tid == 0) red_rel(bar, 1u);
        } else {
            out[myrow * HH + mycol[0]] = hv[0];
            out[myrow * HH + mycol[1]] = hv[1];
            if (out_n >= 2 * NB * HH) {
                out[NB * HH + myrow * HH + mycol[0]] = cst[0];
                out[NB * HH + myrow * HH + mycol[1]] = cst[1];
            }
        }
    }
}

// ================= launch ==================================================
extern "C" void kernel_launch(void* const* d_in, const int* in_sizes, int n_in,
                              void* d_out, int out_size) {
    const float* x    = (const float*)d_in[0];
    const float* w_ii = (const float*)d_in[1];
    const float* w_hi = (const float*)d_in[2];
    const float* w_if = (const float*)d_in[3];
    const float* w_hf = (const float*)d_in[4];
    const float* w_ig = (const float*)d_in[5];
    const float* w_hg = (const float*)d_in[6];
    const float* w_io = (const float*)d_in[7];
    const float* w_ho = (const float*)d_in[8];
    const float* b_ii = (const float*)d_in[9];
    const float* b_hi = (const float*)d_in[10];
    const float* b_if = (const float*)d_in[11];
    const float* b_hf = (const float*)d_in[12];
    const float* b_ig = (const float*)d_in[13];
    const float* b_hg = (const float*)d_in[14];
    const float* b_io = (const float*)d_in[15];
    const float* b_ho = (const float*)d_in[16];
    float* out = (float*)d_out;

    void* barAddr = nullptr;
    cudaGetSymbolAddress(&barAddr, g_bars);
    cudaMemsetAsync(barAddr, 0, 8 * 32 * sizeof(unsigned), 0);

    dim3 g1(16, 1024);
    lstm_xw_kernel<<<g1, 256>>>(x, w_ii, w_if, w_ig, w_io,
                                b_ii, b_hi, b_if, b_hf, b_ig, b_hg, b_io, b_ho);

    lstm_rec_kernel<<<128, 256>>>(w_hi, w_hf, w_hg, w_ho, out, out_size);
}

// round 5
// speedup vs baseline: 1.6095x; 1.1708x over previous
#include <cuda_runtime.h>
#include <cuda_fp16.h>
#include <stdint.h>

#define TT 512
#define NB 256
#define HH 256
#define GG 1024

__device__ float    g_xw[(size_t)TT * NB * GG];
__device__ float    g_h[2 * NB * HH];
__device__ __half   g_wt[4 * 256 * 256];   // [gate][n][k] fp16, transposed weights
__device__ unsigned g_bars[8 * 32];

__device__ __forceinline__ void mma16(float d[4], uint32_t a0, uint32_t a1,
                                      uint32_t a2, uint32_t a3, uint32_t b0, uint32_t b1) {
    asm volatile("mma.sync.aligned.m16n8k16.row.col.f32.f16.f16.f32 "
                 "{%0,%1,%2,%3}, {%4,%5,%6,%7}, {%8,%9}, {%0,%1,%2,%3};\n"
                 : "+f"(d[0]), "+f"(d[1]), "+f"(d[2]), "+f"(d[3])
                 : "r"(a0), "r"(a1), "r"(a2), "r"(a3), "r"(b0), "r"(b1));
}
__device__ __forceinline__ float sigm(float x) { return __fdividef(1.f, 1.f + __expf(-x)); }
__device__ __forceinline__ float tanh_acc(float x) { return 1.f - __fdividef(2.f, __expf(2.f * x) + 1.f); }
__device__ __forceinline__ unsigned ld_acq(const unsigned* p) {
    unsigned v; asm volatile("ld.acquire.gpu.global.u32 %0, [%1];" : "=r"(v) : "l"(p)); return v;
}
__device__ __forceinline__ void red_rel(unsigned* p, unsigned v) {
    asm volatile("red.release.gpu.global.add.u32 [%0], %1;" :: "l"(p), "r"(v) : "memory");
}
__device__ __forceinline__ uint32_t lds_u32h(const __half* p) {
    return *reinterpret_cast<const uint32_t*>(p);
}

// ============ Prep: transpose all W into fp16 [gate][n][k] ================
__global__ void prep_wt(const float* __restrict__ wi, const float* __restrict__ wf,
                        const float* __restrict__ wg, const float* __restrict__ wo) {
    int gt = blockIdx.x >> 8, n = blockIdx.x & 255, k = threadIdx.x;
    const float* w = (gt == 0) ? wi : (gt == 1) ? wf : (gt == 2) ? wg : wo;
    g_wt[(((size_t)gt * 256 + n) << 8) + k] = __float2half_rn(w[k * 256 + n]);
}

// ================= Phase 1: xW = x @ [Wi|Wf|Wg|Wo] + b, fp16 mma ==========
// grid (8, 1024): tile 128 rows x 128 gate-cols (single gate per block), K=256.
// 8 warps: wm = warp>>1 (4 M), wn = warp&1 (2 N). Warp: 32 rows x 64 cols.
#define P1S 40   // smem row stride in halves

__global__ void __launch_bounds__(256) lstm_xw_kernel(
    const float* __restrict__ x,
    const float* __restrict__ bx0, const float* __restrict__ bh0,
    const float* __restrict__ bx1, const float* __restrict__ bh1,
    const float* __restrict__ bx2, const float* __restrict__ bh2,
    const float* __restrict__ bx3, const float* __restrict__ bh3)
{
    __shared__ __half x_s[128 * P1S];
    __shared__ __half w_s[128 * P1S];

    const int tid = threadIdx.x, lane = tid & 31, warp = tid >> 5;
    const int wm = warp >> 1, wn = warp & 1;
    const int u = lane >> 2, r = lane & 3;
    const int row0 = blockIdx.y * 128;
    const int gc0 = blockIdx.x * 128;
    const int gate = gc0 >> 8, jc0 = gc0 & 255;

    const float* bx = (gate == 0) ? bx0 : (gate == 1) ? bx1 : (gate == 2) ? bx2 : bx3;
    const float* bh = (gate == 0) ? bh0 : (gate == 1) ? bh1 : (gate == 2) ? bh2 : bh3;
    const __half* wt = g_wt + ((size_t)gate * 256) * 256;

    float acc[2][8][4];
    #pragma unroll
    for (int i = 0; i < 2; i++)
        #pragma unroll
        for (int j = 0; j < 8; j++)
            #pragma unroll
            for (int k = 0; k < 4; k++) acc[i][j][k] = 0.f;

    const int srow = tid >> 1, shc = (tid & 1) * 16;   // staging coords

    for (int k0 = 0; k0 < 256; k0 += 32) {
        // stage x tile 128 x 32 (fp32 -> fp16)
        {
            const float* src = x + (size_t)(row0 + srow) * 256 + k0 + shc;
            float4 v0 = *(const float4*)(src);
            float4 v1 = *(const float4*)(src + 4);
            float4 v2 = *(const float4*)(src + 8);
            float4 v3 = *(const float4*)(src + 12);
            __half2* d = (__half2*)(x_s + srow * P1S + shc);
            d[0] = __floats2half2_rn(v0.x, v0.y); d[1] = __floats2half2_rn(v0.z, v0.w);
            d[2] = __floats2half2_rn(v1.x, v1.y); d[3] = __floats2half2_rn(v1.z, v1.w);
            d[4] = __floats2half2_rn(v2.x, v2.y); d[5] = __floats2half2_rn(v2.z, v2.w);
            d[6] = __floats2half2_rn(v3.x, v3.y); d[7] = __floats2half2_rn(v3.z, v3.w);
        }
        // stage w tile [n][k] 128 x 32 halves from transposed buffer
        {
            const __half* src = wt + (size_t)(jc0 + srow) * 256 + k0 + shc;
            uint4 v0 = *(const uint4*)(src);
            uint4 v1 = *(const uint4*)(src + 8);
            *(uint4*)(w_s + srow * P1S + shc) = v0;
            *(uint4*)(w_s + srow * P1S + shc + 8) = v1;
        }
        __syncthreads();

        #pragma unroll
        for (int kk = 0; kk < 32; kk += 16) {
            uint32_t a[2][4];
            #pragma unroll
            for (int mt = 0; mt < 2; mt++) {
                int ar = wm * 32 + mt * 16 + u;
                const __half* p0 = x_s + ar * P1S + kk + 2 * r;
                const __half* p1 = x_s + (ar + 8) * P1S + kk + 2 * r;
                a[mt][0] = lds_u32h(p0);
                a[mt][1] = lds_u32h(p1);
                a[mt][2] = lds_u32h(p0 + 8);
                a[mt][3] = lds_u32h(p1 + 8);
            }
            #pragma unroll
            for (int nt = 0; nt < 8; nt++) {
                int bn_ = wn * 64 + nt * 8 + u;
                const __half* pb = w_s + bn_ * P1S + kk + 2 * r;
                uint32_t b0 = lds_u32h(pb);
                uint32_t b1 = lds_u32h(pb + 8);
                mma16(acc[0][nt], a[0][0], a[0][1], a[0][2], a[0][3], b0, b1);
                mma16(acc[1][nt], a[1][0], a[1][1], a[1][2], a[1][3], b0, b1);
            }
        }
        __syncthreads();
    }

    // epilogue: stage 16 cols at a time through smem, write 32B strips
    float* ebuf = (float*)x_s;   // 128 x 18 floats = 9216B, fits
    #pragma unroll
    for (int p = 0; p < 8; p++) {
        int jcol = jc0 + wn * 64 + p * 8 + 2 * r;
        float bs0 = __ldg(bx + jcol)     + __ldg(bh + jcol);
        float bs1 = __ldg(bx + jcol + 1) + __ldg(bh + jcol + 1);
        #pragma unroll
        for (int mt = 0; mt < 2; mt++) {
            int lr = wm * 32 + mt * 16 + u;
            int lc = wn * 8 + 2 * r;
            ebuf[lr * 18 + lc]           = acc[mt][p][0] + bs0;
            ebuf[lr * 18 + lc + 1]       = acc[mt][p][1] + bs1;
            ebuf[(lr + 8) * 18 + lc]     = acc[mt][p][2] + bs0;
            ebuf[(lr + 8) * 18 + lc + 1] = acc[mt][p][3] + bs1;
        }
        __syncthreads();
        #pragma unroll
        for (int it = 0; it < 8; it++) {
            int row  = warp * 16 + it * 2 + (lane >> 4);
            int sc   = (lane >> 3) & 1;
            int col8 = lane & 7;
            int R = row0 + row;
            int t = R & (TT - 1), n = R >> 9;
            g_xw[(size_t)t * (NB * GG) + n * GG + gc0 + sc * 64 + p * 8 + col8] =
                ebuf[row * 18 + sc * 8 + col8];
        }
        __syncthreads();
    }
}

// ================= Phase 2: persistent recurrence, fp16 mma ================
// 128 CTAs: bn = blk>>4, bj = blk&15. 8 warps: wm=warp&1, wc=warp>>1.
// Warp tile 16 rows x 16 vcols (v = jj*4+gt). B(Wh) in 64 packed regs.
#define HSH 264  // h_s row stride in halves
#define XS 68    // xw_s row stride in floats

__global__ void __launch_bounds__(256, 1) lstm_rec_kernel(
    float* __restrict__ out, int out_n)
{
    __shared__ __half h_s[32 * HSH];
    __shared__ float  xw_s[32 * XS];

    const int tid = threadIdx.x, lane = tid & 31, warp = tid >> 5;
    const int wm = warp & 1, wc = warp >> 1;
    const int bn = blockIdx.x >> 4, bj = blockIdx.x & 15;
    const int nBase = bn * 32, j0 = bj * 16;
    const int jw = j0 + wc * 4;
    const int u = lane >> 2, r = lane & 3;
    const int rA = wm * 16 + u;

    unsigned* bar = &g_bars[bn * 32];

    // ---- Wh B fragments from transposed fp16 buffer (contiguous pairs) ----
    uint32_t b0[16][2], b1[16][2];
    #pragma unroll
    for (int nt = 0; nt < 2; nt++) {
        int v = nt * 8 + u;
        int jj = v >> 2, gt = v & 3;
        const __half* wp = g_wt + ((size_t)(gt * 256 + jw + jj)) * 256;
        #pragma unroll
        for (int kc = 0; kc < 16; kc++) {
            b0[kc][nt] = *(const uint32_t*)(wp + kc * 16 + 2 * r);
            b1[kc][nt] = *(const uint32_t*)(wp + kc * 16 + 2 * r + 8);
        }
    }

    // fragment-init LDS offsets for xw (fp32)
    int ioff[2][4];
    #pragma unroll
    for (int nt = 0; nt < 2; nt++)
        #pragma unroll
        for (int sl = 0; sl < 4; sl++) {
            int cc = sl & 1, half = sl >> 1;
            int v = nt * 8 + 2 * r + cc;
            ioff[nt][sl] = (rA + half * 8) * XS + (v & 3) * 16 + wc * 4 + (v >> 2);
        }

    const int odd = lane & 1;
    const int myrow = nBase + rA + (odd ? 8 : 0);
    int mycol[2];
    #pragma unroll
    for (int nt = 0; nt < 2; nt++) mycol[nt] = jw + nt * 2 + (r >> 1);

    const int a0off = rA * HSH + 2 * r;
    const int a1off = (rA + 8) * HSH + 2 * r;

    float cst[2] = {0.f, 0.f};

    for (int t = 0; t < TT; t++) {
        // coalesced xw chunk load (independent of h)
        const float* xwb = g_xw + (size_t)t * (NB * GG) + (size_t)nBase * GG + j0;
        float4 xv[2];
        #pragma unroll
        for (int p = 0; p < 2; p++) {
            int f = p * 256 + tid, seg = f >> 2, w4 = f & 3;
            int row = seg >> 2, gt = seg & 3;
            xv[p] = __ldg((const float4*)(xwb + (size_t)row * GG + gt * 256 + w4 * 4));
        }

        if (t > 0) {
            if (tid == 0) {
                unsigned target = 16u * (unsigned)t;
                while (ld_acq(bar) < target) { }
            }
            __syncthreads();
            // stage h tile fp32 -> fp16
            const float* hsrc = g_h + (t & 1) * (NB * HH) + nBase * HH;
            #pragma unroll
            for (int i = 0; i < 8; i++) {
                int f = i * 256 + tid, row = f >> 6, c4 = (f & 63) << 2;
                float4 v = __ldcg((const float4*)(hsrc + row * HH + c4));
                __half2 p0 = __floats2half2_rn(v.x, v.y);
                __half2 p1 = __floats2half2_rn(v.z, v.w);
                uint2 pk;
                pk.x = *(uint32_t*)&p0; pk.y = *(uint32_t*)&p1;
                *(uint2*)(h_s + row * HSH + c4) = pk;
            }
        }
        // stage xw chunk
        #pragma unroll
        for (int p = 0; p < 2; p++) {
            int f = p * 256 + tid, seg = f >> 2, w4 = f & 3;
            int row = seg >> 2, gt = seg & 3;
            *(float4*)(xw_s + row * XS + gt * 16 + w4 * 4) = xv[p];
        }
        __syncthreads();

        float acc[2][4];
        #pragma unroll
        for (int nt = 0; nt < 2; nt++)
            #pragma unroll
            for (int sl = 0; sl < 4; sl++)
                acc[nt][sl] = xw_s[ioff[nt][sl]];

        if (t > 0) {
            #pragma unroll
            for (int kc = 0; kc < 16; kc++) {
                const int kh = kc * 16;
                uint32_t a0 = lds_u32h(h_s + a0off + kh);
                uint32_t a1 = lds_u32h(h_s + a1off + kh);
                uint32_t a2 = lds_u32h(h_s + a0off + kh + 8);
                uint32_t a3 = lds_u32h(h_s + a1off + kh + 8);
                mma16(acc[0], a0, a1, a2, a3, b0[kc][0], b1[kc][0]);
                mma16(acc[1], a0, a1, a2, a3, b0[kc][1], b1[kc][1]);
            }
        }

        // epilogue: lane-pair gate exchange + cell update
        float hv[2];
        #pragma unroll
        for (int nt = 0; nt < 2; nt++) {
            float s0 = odd ? acc[nt][0] : acc[nt][2];
            float s1 = odd ? acc[nt][1] : acc[nt][3];
            float r0 = __shfl_xor_sync(0xFFFFFFFFu, s0, 1);
            float r1 = __shfl_xor_sync(0xFFFFFFFFu, s1, 1);
            float iv, fv, gv, ov;
            if (odd) { iv = r0; fv = r1; gv = acc[nt][2]; ov = acc[nt][3]; }
            else     { iv = acc[nt][0]; fv = acc[nt][1]; gv = r0; ov = r1; }
            float ig = sigm(iv), fg = sigm(fv), gg = tanh_acc(gv), og = sigm(ov);
            float c = fg * cst[nt] + ig * gg;
            cst[nt] = c;
            hv[nt] = og * tanh_acc(c);
        }

        if (t < TT - 1) {
            float* hdst = g_h + ((t + 1) & 1) * (NB * HH) + myrow * HH;
            __stcg(hdst + mycol[0], hv[0]);
            __stcg(hdst + mycol[1], hv[1]);
            __syncthreads();
            if (tid == 0) red_rel(bar, 1u);
        } else {
            out[myrow * HH + mycol[0]] = hv[0];
            out[myrow * HH + mycol[1]] = hv[1];
            if (out_n >= 2 * NB * HH) {
                out[NB * HH + myrow * HH + mycol[0]] = cst[0];
                out[NB * HH + myrow * HH + mycol[1]] = cst[1];
            }
        }
    }
}

// ================= launch ==================================================
extern "C" void kernel_launch(void* const* d_in, const int* in_sizes, int n_in,
                              void* d_out, int out_size) {
    const float* x    = (const float*)d_in[0];
    const float* w_ii = (const float*)d_in[1];
    const float* w_hi = (const float*)d_in[2];
    const float* w_if = (const float*)d_in[3];
    const float* w_hf = (const float*)d_in[4];
    const float* w_ig = (const float*)d_in[5];
    const float* w_hg = (const float*)d_in[6];
    const float* w_io = (const float*)d_in[7];
    const float* w_ho = (const float*)d_in[8];
    const float* b_ii = (const float*)d_in[9];
    const float* b_hi = (const float*)d_in[10];
    const float* b_if = (const float*)d_in[11];
    const float* b_hf = (const float*)d_in[12];
    const float* b_ig = (const float*)d_in[13];
    const float* b_hg = (const float*)d_in[14];
    const float* b_io = (const float*)d_in[15];
    const float* b_ho = (const float*)d_in[16];
    float* out = (float*)d_out;

    void* barAddr = nullptr;
    cudaGetSymbolAddress(&barAddr, g_bars);
    cudaMemsetAsync(barAddr, 0, 8 * 32 * sizeof(unsigned), 0);

    // transpose hidden weights (for phase-2 B regs) and input weights (phase-1)
    prep_wt<<<1024, 256>>>(w_hi, w_hf, w_hg, w_ho);       // g_wt <- Wh (used by rec)
    // Phase-1 needs Wx transposed; use a second region? No — phase 1 consumes
    // g_wt BEFORE rec runs. Order: prep Wx -> xw kernel -> prep Wh -> rec.
    // Relaunch prep with Wx first:
    // (overwrite: prep Wx, run phase1, then prep Wh, then rec)
    prep_wt<<<1024, 256>>>(w_ii, w_if, w_ig, w_io);       // g_wt <- Wx

    dim3 g1(8, 1024);
    lstm_xw_kernel<<<g1, 256>>>(x, b_ii, b_hi, b_if, b_hf, b_ig, b_hg, b_io, b_ho);

    prep_wt<<<1024, 256>>>(w_hi, w_hf, w_hg, w_ho);       // g_wt <- Wh

    lstm_rec_kernel<<<128, 256>>>(out, out_size);
}

// round 6
// speedup vs baseline: 1.9077x; 1.1852x over previous
#include <cuda_runtime.h>
#include <cuda_fp16.h>
#include <stdint.h>

#define TT 512
#define NB 256
#define HH 256
#define GG 1024

// vcol = jj*4 + gate  (jj = hidden col, gate: 0=i 1=f 2=g 3=o)
__device__ float    g_xw[(size_t)TT * NB * GG];   // [t][n][vcol]
__device__ __half   g_hh[2 * NB * HH];            // fp16 hidden state, double buffered
__device__ __half   g_wtx[1024 * 256];            // [vcol][k] Wx fp16
__device__ __half   g_wth[1024 * 256];            // [vcol][k] Wh fp16
__device__ float    g_bvc[1024];                  // combined bias per vcol
__device__ unsigned g_bars[8 * 32];

__device__ __forceinline__ void mma16(float d[4], uint32_t a0, uint32_t a1,
                                      uint32_t a2, uint32_t a3, uint32_t b0, uint32_t b1) {
    asm volatile("mma.sync.aligned.m16n8k16.row.col.f32.f16.f16.f32 "
                 "{%0,%1,%2,%3}, {%4,%5,%6,%7}, {%8,%9}, {%0,%1,%2,%3};\n"
                 : "+f"(d[0]), "+f"(d[1]), "+f"(d[2]), "+f"(d[3])
                 : "r"(a0), "r"(a1), "r"(a2), "r"(a3), "r"(b0), "r"(b1));
}
__device__ __forceinline__ float sigm(float x) { return __fdividef(1.f, 1.f + __expf(-x)); }
__device__ __forceinline__ float tanh_acc(float x) { return 1.f - __fdividef(2.f, __expf(2.f * x) + 1.f); }
__device__ __forceinline__ unsigned ld_acq(const unsigned* p) {
    unsigned v; asm volatile("ld.acquire.gpu.global.u32 %0, [%1];" : "=r"(v) : "l"(p)); return v;
}
__device__ __forceinline__ void red_rel(unsigned* p, unsigned v) {
    asm volatile("red.release.gpu.global.add.u32 [%0], %1;" :: "l"(p), "r"(v) : "memory");
}
__device__ __forceinline__ uint32_t lds_u32h(const __half* p) {
    return *reinterpret_cast<const uint32_t*>(p);
}

// ============ Prep: weights -> fp16 [vcol][k]; combined bias ===============
__global__ void prep_w(const float* __restrict__ xi, const float* __restrict__ xf,
                       const float* __restrict__ xg, const float* __restrict__ xo,
                       const float* __restrict__ hi, const float* __restrict__ hf,
                       const float* __restrict__ hg, const float* __restrict__ ho) {
    int which = blockIdx.x >> 10, vv = blockIdx.x & 1023;
    int jj = vv >> 2, gt = vv & 3, k = threadIdx.x;
    const float* w;
    if (which == 0) w = (gt == 0) ? xi : (gt == 1) ? xf : (gt == 2) ? xg : xo;
    else            w = (gt == 0) ? hi : (gt == 1) ? hf : (gt == 2) ? hg : ho;
    __half* dst = which == 0 ? g_wtx : g_wth;
    dst[((size_t)vv << 8) + k] = __float2half_rn(w[k * 256 + jj]);
}
__global__ void prep_b(const float* __restrict__ b0, const float* __restrict__ b1,
                       const float* __restrict__ b2, const float* __restrict__ b3,
                       const float* __restrict__ b4, const float* __restrict__ b5,
                       const float* __restrict__ b6, const float* __restrict__ b7) {
    int vv = blockIdx.x * 256 + threadIdx.x;
    int jj = vv >> 2, gt = vv & 3;
    const float* bx = (gt == 0) ? b0 : (gt == 1) ? b2 : (gt == 2) ? b4 : b6;
    const float* bh = (gt == 0) ? b1 : (gt == 1) ? b3 : (gt == 2) ? b5 : b7;
    g_bvc[vv] = bx[jj] + bh[jj];
}

// ================= Phase 1: xW(+b) in vcol order, fp16 mma =================
// grid (8, 1024): 128 rows x 128 vcols, K=256. 8 warps: wm=warp>>1, wn=warp&1.
#define P1S 40

__global__ void __launch_bounds__(256) lstm_xw_kernel(const float* __restrict__ x)
{
    __shared__ __half x_s[128 * P1S];
    __shared__ __half w_s[128 * P1S];

    const int tid = threadIdx.x, lane = tid & 31, warp = tid >> 5;
    const int wm = warp >> 1, wn = warp & 1;
    const int u = lane >> 2, r = lane & 3;
    const int row0 = blockIdx.y * 128;
    const int vc0 = blockIdx.x * 128;
    const __half* wt = g_wtx + (size_t)vc0 * 256;

    float acc[2][8][4];
    #pragma unroll
    for (int i = 0; i < 2; i++)
        #pragma unroll
        for (int j = 0; j < 8; j++)
            #pragma unroll
            for (int k = 0; k < 4; k++) acc[i][j][k] = 0.f;

    const int srow = tid >> 1, shc = (tid & 1) * 16;

    for (int k0 = 0; k0 < 256; k0 += 32) {
        {
            const float* src = x + (size_t)(row0 + srow) * 256 + k0 + shc;
            float4 v0 = *(const float4*)(src);
            float4 v1 = *(const float4*)(src + 4);
            float4 v2 = *(const float4*)(src + 8);
            float4 v3 = *(const float4*)(src + 12);
            __half2* d = (__half2*)(x_s + srow * P1S + shc);
            d[0] = __floats2half2_rn(v0.x, v0.y); d[1] = __floats2half2_rn(v0.z, v0.w);
            d[2] = __floats2half2_rn(v1.x, v1.y); d[3] = __floats2half2_rn(v1.z, v1.w);
            d[4] = __floats2half2_rn(v2.x, v2.y); d[5] = __floats2half2_rn(v2.z, v2.w);
            d[6] = __floats2half2_rn(v3.x, v3.y); d[7] = __floats2half2_rn(v3.z, v3.w);
        }
        {
            const __half* src = wt + (size_t)srow * 256 + k0 + shc;
            uint4 v0 = *(const uint4*)(src);
            uint4 v1 = *(const uint4*)(src + 8);
            *(uint4*)(w_s + srow * P1S + shc) = v0;
            *(uint4*)(w_s + srow * P1S + shc + 8) = v1;
        }
        __syncthreads();

        #pragma unroll
        for (int kk = 0; kk < 32; kk += 16) {
            uint32_t a[2][4];
            #pragma unroll
            for (int mt = 0; mt < 2; mt++) {
                int ar = wm * 32 + mt * 16 + u;
                const __half* p0 = x_s + ar * P1S + kk + 2 * r;
                const __half* p1 = x_s + (ar + 8) * P1S + kk + 2 * r;
                a[mt][0] = lds_u32h(p0);
                a[mt][1] = lds_u32h(p1);
                a[mt][2] = lds_u32h(p0 + 8);
                a[mt][3] = lds_u32h(p1 + 8);
            }
            #pragma unroll
            for (int nt = 0; nt < 8; nt++) {
                int bn_ = wn * 64 + nt * 8 + u;
                const __half* pb = w_s + bn_ * P1S + kk + 2 * r;
                uint32_t b0 = lds_u32h(pb);
                uint32_t b1 = lds_u32h(pb + 8);
                mma16(acc[0][nt], a[0][0], a[0][1], a[0][2], a[0][3], b0, b1);
                mma16(acc[1][nt], a[1][0], a[1][1], a[1][2], a[1][3], b0, b1);
            }
        }
        __syncthreads();
    }

    float* ebuf = (float*)x_s;
    #pragma unroll
    for (int p = 0; p < 8; p++) {
        int jcol = vc0 + wn * 64 + p * 8 + 2 * r;
        float bs0 = __ldg(g_bvc + jcol);
        float bs1 = __ldg(g_bvc + jcol + 1);
        #pragma unroll
        for (int mt = 0; mt < 2; mt++) {
            int lr = wm * 32 + mt * 16 + u;
            int lc = wn * 8 + 2 * r;
            ebuf[lr * 18 + lc]           = acc[mt][p][0] + bs0;
            ebuf[lr * 18 + lc + 1]       = acc[mt][p][1] + bs1;
            ebuf[(lr + 8) * 18 + lc]     = acc[mt][p][2] + bs0;
            ebuf[(lr + 8) * 18 + lc + 1] = acc[mt][p][3] + bs1;
        }
        __syncthreads();
        #pragma unroll
        for (int it = 0; it < 8; it++) {
            int row  = warp * 16 + it * 2 + (lane >> 4);
            int sc   = (lane >> 3) & 1;
            int col8 = lane & 7;
            int R = row0 + row;
            int t = R & (TT - 1), n = R >> 9;
            g_xw[(size_t)t * (NB * GG) + n * GG + vc0 + sc * 64 + p * 8 + col8] =
                ebuf[row * 18 + sc * 8 + col8];
        }
        __syncthreads();
    }
}

// ================= Phase 2: persistent recurrence ==========================
// 128 CTAs: bn=blk>>4, bj=blk&15. 8 warps: wm=warp&1, wc=warp>>1.
// Warp: 16 rows x 16 contiguous vcols. B(Wh) in 64 packed regs.
// xw: fragment-direct LDG.64, pipelined one step ahead. h: fp16.
#define HSH 264

__global__ void __launch_bounds__(256, 1) lstm_rec_kernel(
    float* __restrict__ out, int out_n)
{
    __shared__ __half h_s[32 * HSH];
    __shared__ float  hx_s[32 * 16];

    const int tid = threadIdx.x, lane = tid & 31, warp = tid >> 5;
    const int wm = warp & 1, wc = warp >> 1;
    const int bn = blockIdx.x >> 4, bj = blockIdx.x & 15;
    const int nBase = bn * 32, j0 = bj * 16;
    const int jw = j0 + wc * 4;
    const int u = lane >> 2, r = lane & 3;
    const int rA = wm * 16 + u;

    unsigned* bar = &g_bars[bn * 32];

    // ---- Wh B fragments (vcol-contiguous rows) ----
    uint32_t b0[16][2], b1[16][2];
    #pragma unroll
    for (int nt = 0; nt < 2; nt++) {
        const __half* wp = g_wth + ((size_t)(bj * 64 + wc * 16 + nt * 8 + u)) * 256;
        #pragma unroll
        for (int kc = 0; kc < 16; kc++) {
            b0[kc][nt] = *(const uint32_t*)(wp + kc * 16 + 2 * r);
            b1[kc][nt] = *(const uint32_t*)(wp + kc * 16 + 2 * r + 8);
        }
    }

    const int odd = lane & 1;
    const int lrow = rA + (odd ? 8 : 0);          // local row this lane finalizes
    const int myrow = nBase + lrow;
    int lcol[2];
    #pragma unroll
    for (int nt = 0; nt < 2; nt++) lcol[nt] = wc * 4 + nt * 2 + (r >> 1);

    const int a0off = rA * HSH + 2 * r;
    const int a1off = (rA + 8) * HSH + 2 * r;

    // xw fragment pointer: row nBase+rA, vcols bj*64 + wc*16 + 2r
    const float* xwp0 = g_xw + (size_t)(nBase + rA) * GG + bj * 64 + wc * 16 + 2 * r;

    float cst[2] = {0.f, 0.f};

    // prime prefetch for t=0
    float2 xv[2][2];
    {
        const float* p = xwp0;
        xv[0][0] = __ldg((const float2*)(p));
        xv[1][0] = __ldg((const float2*)(p + 8));
        xv[0][1] = __ldg((const float2*)(p + 8 * GG));
        xv[1][1] = __ldg((const float2*)(p + 8 * GG + 8));
    }

    for (int t = 0; t < TT; t++) {
        // consume prefetched xw into accumulators
        float acc[2][4];
        #pragma unroll
        for (int nt = 0; nt < 2; nt++) {
            acc[nt][0] = xv[nt][0].x; acc[nt][1] = xv[nt][0].y;
            acc[nt][2] = xv[nt][1].x; acc[nt][3] = xv[nt][1].y;
        }
        // issue prefetch for t+1 (latency hidden by barrier+stage+mma)
        if (t + 1 < TT) {
            const float* p = xwp0 + (size_t)(t + 1) * (NB * GG);
            xv[0][0] = __ldg((const float2*)(p));
            xv[1][0] = __ldg((const float2*)(p + 8));
            xv[0][1] = __ldg((const float2*)(p + 8 * GG));
            xv[1][1] = __ldg((const float2*)(p + 8 * GG + 8));
        }

        if (t > 0) {
            if (tid == 0) {
                unsigned target = 16u * (unsigned)t;
                while (ld_acq(bar) < target) { }
            }
            __syncthreads();
            // stage h tile (fp16, no conversion): 32 rows x 256 halves
            const __half* hsrc = g_hh + (t & 1) * (NB * HH) + nBase * HH;
            #pragma unroll
            for (int i = 0; i < 4; i++) {
                int f = i * 256 + tid, row = f >> 5, c8 = (f & 31) << 3;
                uint4 v = __ldcg((const uint4*)(hsrc + row * HH + c8));
                *(uint4*)(h_s + row * HSH + c8) = v;
            }
            __syncthreads();

            #pragma unroll
            for (int kc = 0; kc < 16; kc++) {
                const int kh = kc * 16;
                uint32_t a0 = lds_u32h(h_s + a0off + kh);
                uint32_t a1 = lds_u32h(h_s + a1off + kh);
                uint32_t a2 = lds_u32h(h_s + a0off + kh + 8);
                uint32_t a3 = lds_u32h(h_s + a1off + kh + 8);
                mma16(acc[0], a0, a1, a2, a3, b0[kc][0], b1[kc][0]);
                mma16(acc[1], a0, a1, a2, a3, b0[kc][1], b1[kc][1]);
            }
        }

        // epilogue: lane-pair gate exchange + cell update
        float hv[2];
        #pragma unroll
        for (int nt = 0; nt < 2; nt++) {
            float s0 = odd ? acc[nt][0] : acc[nt][2];
            float s1 = odd ? acc[nt][1] : acc[nt][3];
            float r0 = __shfl_xor_sync(0xFFFFFFFFu, s0, 1);
            float r1 = __shfl_xor_sync(0xFFFFFFFFu, s1, 1);
            float iv, fv, gv, ov;
            if (odd) { iv = r0; fv = r1; gv = acc[nt][2]; ov = acc[nt][3]; }
            else     { iv = acc[nt][0]; fv = acc[nt][1]; gv = r0; ov = r1; }
            float ig = sigm(iv), fg = sigm(fv), gg = tanh_acc(gv), og = sigm(ov);
            float c = fg * cst[nt] + ig * gg;
            cst[nt] = c;
            hv[nt] = og * tanh_acc(c);
        }

        if (t < TT - 1) {
            // bounce hv through smem -> coalesced fp16 STG.128
            hx_s[lrow * 16 + lcol[0]] = hv[0];
            hx_s[lrow * 16 + lcol[1]] = hv[1];
            __syncthreads();
            if (tid < 64) {
                int row = tid >> 1, part = tid & 1;
                const float* s = hx_s + row * 16 + part * 8;
                __half2 h0 = __floats2half2_rn(s[0], s[1]);
                __half2 h1 = __floats2half2_rn(s[2], s[3]);
                __half2 h2 = __floats2half2_rn(s[4], s[5]);
                __half2 h3 = __floats2half2_rn(s[6], s[7]);
                uint4 pk;
                pk.x = *(uint32_t*)&h0; pk.y = *(uint32_t*)&h1;
                pk.z = *(uint32_t*)&h2; pk.w = *(uint32_t*)&h3;
                __half* hdst = g_hh + ((t + 1) & 1) * (NB * HH)
                             + (nBase + row) * HH + j0 + part * 8;
                __stcg((uint4*)hdst, pk);
            }
            __syncthreads();
            if (tid == 0) red_rel(bar, 1u);
        } else {
            out[myrow * HH + j0 + lcol[0]] = hv[0];
            out[myrow * HH + j0 + lcol[1]] = hv[1];
            if (out_n >= 2 * NB * HH) {
                out[NB * HH + myrow * HH + j0 + lcol[0]] = cst[0];
                out[NB * HH + myrow * HH + j0 + lcol[1]] = cst[1];
            }
        }
    }
}

// ================= launch ==================================================
extern "C" void kernel_launch(void* const* d_in, const int* in_sizes, int n_in,
                              void* d_out, int out_size) {
    const float* x    = (const float*)d_in[0];
    const float* w_ii = (const float*)d_in[1];
    const float* w_hi = (const float*)d_in[2];
    const float* w_if = (const float*)d_in[3];
    const float* w_hf = (const float*)d_in[4];
    const float* w_ig = (const float*)d_in[5];
    const float* w_hg = (const float*)d_in[6];
    const float* w_io = (const float*)d_in[7];
    const float* w_ho = (const float*)d_in[8];
    const float* b_ii = (const float*)d_in[9];
    const float* b_hi = (const float*)d_in[10];
    const float* b_if = (const float*)d_in[11];
    const float* b_hf = (const float*)d_in[12];
    const float* b_ig = (const float*)d_in[13];
    const float* b_hg = (const float*)d_in[14];
    const float* b_io = (const float*)d_in[15];
    const float* b_ho = (const float*)d_in[16];
    float* out = (float*)d_out;

    void* barAddr = nullptr;
    cudaGetSymbolAddress(&barAddr, g_bars);
    cudaMemsetAsync(barAddr, 0, 8 * 32 * sizeof(unsigned), 0);

    prep_w<<<2048, 256>>>(w_ii, w_if, w_ig, w_io, w_hi, w_hf, w_hg, w_ho);
    prep_b<<<4, 256>>>(b_ii, b_hi, b_if, b_hf, b_ig, b_hg, b_io, b_ho);

    dim3 g1(8, 1024);
    lstm_xw_kernel<<<g1, 256>>>(x);

    lstm_rec_kernel<<<128, 256>>>(out, out_size);
}